// round 5
// baseline (speedup 1.0000x reference)
#include <cuda_runtime.h>
#include <cuda_fp16.h>
#include <cstddef>
#include <cstdint>

#define BATCH 8
#define CH    512
#define TOK   1024
#define HEADS 8
#define HD    64
#define NHEAD (BATCH*HEADS)   // 64
#define GROUPS 32
#define CPG   16

#define QSCALE 0.1803368801111204f   // 0.125 * log2(e)
#define SM_OFF 4.0f                  // static softmax shift (log2 domain)

// ---------------- scratch (__device__ globals; alloc-free rule) -------------
__device__ __align__(16) __half g_nT  [(size_t)BATCH*TOK*CH];    // [b][t][c]
__device__ __align__(16) __half g_wqkv[(size_t)3*CH*CH];         // [och][c]
__device__ __align__(16) __half g_wout[(size_t)CH*CH];           // [och][c]
__device__ __align__(16) __half g_q   [(size_t)NHEAD*TOK*HD];    // [head][t][c]  (x QSCALE)
__device__ __align__(16) __half g_k   [(size_t)NHEAD*TOK*HD];    // [head][s][c]
__device__ __align__(16) __half g_v   [(size_t)NHEAD*HD*TOK];    // [head][c][s]
__device__ __align__(16) __half g_netT[(size_t)BATCH*TOK*CH];    // [b][t][c]

// ---------------- helpers ---------------------------------------------------
__device__ __forceinline__ void mma_f16(float* c, const uint32_t* a, const uint32_t* b)
{
    asm volatile(
        "mma.sync.aligned.m16n8k16.row.col.f32.f16.f16.f32 "
        "{%0,%1,%2,%3},{%4,%5,%6,%7},{%8,%9},{%0,%1,%2,%3};"
        : "+f"(c[0]), "+f"(c[1]), "+f"(c[2]), "+f"(c[3])
        : "r"(a[0]), "r"(a[1]), "r"(a[2]), "r"(a[3]), "r"(b[0]), "r"(b[1]));
}

__device__ __forceinline__ uint32_t pack_h2(float lo, float hi)
{
    __half2 h = __floats2half2_rn(lo, hi);
    return *reinterpret_cast<uint32_t*>(&h);
}

__device__ __forceinline__ float ex2(float x)
{
    float y;
    asm("ex2.approx.ftz.f32 %0, %1;" : "=f"(y) : "f"(x));
    return y;
}

__device__ __forceinline__ void cp16(void* s, const void* g)
{
    uint32_t sa = (uint32_t)__cvta_generic_to_shared(s);
    asm volatile("cp.async.cg.shared.global [%0], [%1], 16;\n" :: "r"(sa), "l"(g));
}
#define CP_COMMIT() asm volatile("cp.async.commit_group;\n" ::: "memory")
#define CP_WAIT1()  asm volatile("cp.async.wait_group 1;\n" ::: "memory")
#define CP_WAIT0()  asm volatile("cp.async.wait_group 0;\n" ::: "memory")

// ---------------------------------------------------------------------------
// Kernel 0: convert weights fp32 -> fp16
// ---------------------------------------------------------------------------
__global__ void cvt_w_kernel(const float* __restrict__ qkvw,
                             const float* __restrict__ outw)
{
    int i = blockIdx.x * 256 + threadIdx.x;
    const int N1 = 3*CH*CH/4;
    const int N2 = CH*CH/4;
    if (i < N1) {
        float4 v = *(const float4*)(qkvw + (size_t)i*4);
        __half* d = g_wqkv + (size_t)i*4;
        d[0]=__float2half_rn(v.x); d[1]=__float2half_rn(v.y);
        d[2]=__float2half_rn(v.z); d[3]=__float2half_rn(v.w);
    } else if (i < N1 + N2) {
        int j = i - N1;
        float4 v = *(const float4*)(outw + (size_t)j*4);
        __half* d = g_wout + (size_t)j*4;
        d[0]=__float2half_rn(v.x); d[1]=__float2half_rn(v.y);
        d[2]=__float2half_rn(v.z); d[3]=__float2half_rn(v.w);
    }
}

// ---------------------------------------------------------------------------
// Kernel 1: GroupNorm -> g_nT[b][t][c] (half), transposed via smem tiles.
// ---------------------------------------------------------------------------
__global__ void gn_kernel(const float* __restrict__ x,
                          const float* __restrict__ w,
                          const float* __restrict__ bb)
{
    int blk = blockIdx.x;
    int b = blk >> 5, gg = blk & 31;
    const float* src = x + ((size_t)b*CH + gg*CPG) * TOK;
    int tid = threadIdx.x;
    const int N = CPG * TOK;   // 16384

    float s = 0.f, ss = 0.f;
    for (int i = tid*4; i < N; i += 256*4) {
        float4 v = *(const float4*)(src + i);
        s  += v.x + v.y + v.z + v.w;
        ss += v.x*v.x + v.y*v.y + v.z*v.z + v.w*v.w;
    }
    for (int o = 16; o; o >>= 1) {
        s  += __shfl_down_sync(~0u, s,  o);
        ss += __shfl_down_sync(~0u, ss, o);
    }
    __shared__ float shs[8], shq[8];
    __shared__ float f_mu, f_rstd;
    if ((tid & 31) == 0) { shs[tid>>5] = s; shq[tid>>5] = ss; }
    __syncthreads();
    if (tid == 0) {
        float ts = 0.f, tq = 0.f;
        #pragma unroll
        for (int i = 0; i < 8; i++) { ts += shs[i]; tq += shq[i]; }
        float mu  = ts / N;
        f_mu = mu;
        f_rstd = rsqrtf(tq / N - mu*mu + 1e-5f);
    }
    __syncthreads();
    float mu = f_mu, rstd = f_rstd;

    __shared__ __align__(16) __half tile[16][68];
    int c  = tid >> 4;
    int tl = (tid & 15) * 4;
    float scw = w[gg*CPG + c] * rstd;
    float scb = bb[gg*CPG + c] - mu * scw;
    int tw  = tid >> 2;
    int c4  = (tid & 3) * 4;
    for (int t0 = 0; t0 < TOK; t0 += 64) {
        float4 v = *(const float4*)(src + (size_t)c*TOK + t0 + tl);
        __half2 h0 = __floats2half2_rn(v.x*scw+scb, v.y*scw+scb);
        __half2 h1 = __floats2half2_rn(v.z*scw+scb, v.w*scw+scb);
        *(__half2*)&tile[c][tl]   = h0;
        *(__half2*)&tile[c][tl+2] = h1;
        __syncthreads();
        __half* dst = g_nT + ((size_t)b*TOK + t0 + tw)*CH + gg*CPG + c4;
        *(__half2*)(dst)   = __halves2half2(tile[c4  ][tw], tile[c4+1][tw]);
        *(__half2*)(dst+2) = __halves2half2(tile[c4+2][tw], tile[c4+3][tw]);
        __syncthreads();
    }
}

// ---------------------------------------------------------------------------
// Kernel 2/4: half GEMM, C[m][n] = sum_k A[m][k] * B[n][k], K=512.
// 128x128 block tile, 8 warps, double-buffered smem via cp.async.
// ---------------------------------------------------------------------------
template<int MODE>
__global__ void __launch_bounds__(256)
gemm_h(const __half* __restrict__ Abase, const __half* __restrict__ Bbase,
       const float* __restrict__ bias, const float* __restrict__ res,
       float* __restrict__ Cout)
{
    __shared__ __align__(16) __half As[2][128][40];
    __shared__ __align__(16) __half Bs[2][128][40];

    int bz = blockIdx.z;
    const __half* A = Abase + (MODE == 0 ? (size_t)bz*TOK*CH : 0);
    const __half* B = Bbase + (MODE == 1 ? (size_t)bz*TOK*CH : 0);

    int m0 = blockIdx.y * 128, n0 = blockIdx.x * 128;
    int tid = threadIdx.x, wid = tid >> 5, lane = tid & 31;
    int g = lane >> 2, tg = lane & 3;
    int wm = wid & 3, wn = wid >> 2;

    int lr = tid >> 2;
    int lc = (tid & 3) * 8;

    cp16(&As[0][lr   ][lc], A + (size_t)(m0+lr   )*CH + lc);
    cp16(&As[0][lr+64][lc], A + (size_t)(m0+lr+64)*CH + lc);
    cp16(&Bs[0][lr   ][lc], B + (size_t)(n0+lr   )*CH + lc);
    cp16(&Bs[0][lr+64][lc], B + (size_t)(n0+lr+64)*CH + lc);
    CP_COMMIT();

    float acc[2][8][4] = {};

    for (int ks = 0; ks < 16; ks++) {
        int buf = ks & 1;
        if (ks + 1 < 16) {
            int k1 = (ks+1) * 32;
            cp16(&As[buf^1][lr   ][lc], A + (size_t)(m0+lr   )*CH + k1 + lc);
            cp16(&As[buf^1][lr+64][lc], A + (size_t)(m0+lr+64)*CH + k1 + lc);
            cp16(&Bs[buf^1][lr   ][lc], B + (size_t)(n0+lr   )*CH + k1 + lc);
            cp16(&Bs[buf^1][lr+64][lc], B + (size_t)(n0+lr+64)*CH + k1 + lc);
            CP_COMMIT();
            CP_WAIT1();
        } else {
            CP_WAIT0();
        }
        __syncthreads();
        #pragma unroll
        for (int kk = 0; kk < 2; kk++) {
            uint32_t af[2][4], bf[8][2];
            int kc = kk*16 + tg*2;
            #pragma unroll
            for (int i = 0; i < 2; i++) {
                int mr = wm*32 + i*16 + g;
                af[i][0] = *(const uint32_t*)&As[buf][mr  ][kc];
                af[i][1] = *(const uint32_t*)&As[buf][mr+8][kc];
                af[i][2] = *(const uint32_t*)&As[buf][mr  ][kc+8];
                af[i][3] = *(const uint32_t*)&As[buf][mr+8][kc+8];
            }
            #pragma unroll
            for (int j = 0; j < 8; j++) {
                int nr = wn*64 + j*8 + g;
                bf[j][0] = *(const uint32_t*)&Bs[buf][nr][kc];
                bf[j][1] = *(const uint32_t*)&Bs[buf][nr][kc+8];
            }
            #pragma unroll
            for (int i = 0; i < 2; i++)
                #pragma unroll
                for (int j = 0; j < 8; j++)
                    mma_f16(acc[i][j], af[i], bf[j]);
        }
        __syncthreads();
    }

    if (MODE == 0) {
        #pragma unroll
        for (int j = 0; j < 8; j++) {
            int n = n0 + wn*64 + j*8 + tg*2;      // och
            float bi0 = bias[n], bi1 = bias[n+1];
            int hh = n / 192, r = n % 192;
            #pragma unroll
            for (int i = 0; i < 2; i++) {
                int t = m0 + wm*32 + i*16 + g;
                float v00 = acc[i][j][0]+bi0, v01 = acc[i][j][1]+bi1;
                float v10 = acc[i][j][2]+bi0, v11 = acc[i][j][3]+bi1;
                size_t hb = (size_t)(bz*HEADS + hh);
                if (r < 64) {
                    v00*=QSCALE; v01*=QSCALE; v10*=QSCALE; v11*=QSCALE;
                    __half* q = g_q + (hb*TOK)*HD + r;
                    *(__half2*)(q + (size_t)t    *HD) = __floats2half2_rn(v00, v01);
                    *(__half2*)(q + (size_t)(t+8)*HD) = __floats2half2_rn(v10, v11);
                } else if (r < 128) {
                    __half* k = g_k + (hb*TOK)*HD + (r-64);
                    *(__half2*)(k + (size_t)t    *HD) = __floats2half2_rn(v00, v01);
                    *(__half2*)(k + (size_t)(t+8)*HD) = __floats2half2_rn(v10, v11);
                } else {
                    int cc = r - 128;
                    __half* v = g_v + (hb*HD + cc)*TOK;
                    v[t]         = __float2half_rn(v00);
                    v[TOK + t]   = __float2half_rn(v01);
                    v[t+8]       = __float2half_rn(v10);
                    v[TOK + t+8] = __float2half_rn(v11);
                }
            }
        }
    } else {
        #pragma unroll
        for (int j = 0; j < 8; j++) {
            int n = n0 + wn*64 + j*8 + tg*2;
            #pragma unroll
            for (int i = 0; i < 2; i++) {
                int m = m0 + wm*32 + i*16 + g;
                float ob0 = bias[m], ob1 = bias[m+8];
                size_t o0 = ((size_t)bz*CH + m)*TOK + n;
                size_t o1 = ((size_t)bz*CH + m+8)*TOK + n;
                float2 r0 = *(const float2*)(res + o0);
                float2 r1 = *(const float2*)(res + o1);
                float2 w0 = { acc[i][j][0]+ob0+r0.x, acc[i][j][1]+ob0+r0.y };
                float2 w1 = { acc[i][j][2]+ob1+r1.x, acc[i][j][3]+ob1+r1.y };
                *(float2*)(Cout + o0) = w0;
                *(float2*)(Cout + o1) = w1;
            }
        }
    }
}

// ---------------------------------------------------------------------------
// Kernel 3: flash attention, static-max softmax (shift-invariant, fixed -4
// shift in log2 domain), deferred sum reduction, no accumulator rescale.
// Block = (head, 128 q-rows), 256 threads / 8 warps, each warp 16 q-rows.
// K/V double-buffered via cp.async.
// ---------------------------------------------------------------------------
__global__ void __launch_bounds__(256) flash_kernel()
{
    int head = blockIdx.y;
    int b = head >> 3, h = head & 7;
    int t0 = blockIdx.x * 128;
    const __half* Qg = g_q + ((size_t)head*TOK + t0)*HD;
    const __half* Kg = g_k + (size_t)head*TOK*HD;
    const __half* Vg = g_v + (size_t)head*HD*TOK;

    __shared__ __align__(16) __half Qs[128][72];
    __shared__ __align__(16) __half Ks[2][64][72];
    __shared__ __align__(16) __half Vs[2][64][72];

    int tid = threadIdx.x, wid = tid >> 5, lane = tid & 31;
    int g = lane >> 2, tg = lane & 3;

    // load Q tile (128 rows x 64)
    #pragma unroll
    for (int p = 0; p < 4; p++) {
        int u = tid + p*256;
        int r = u >> 3, cg = (u & 7) * 8;
        *(uint4*)&Qs[r][cg] = *(const uint4*)(Qg + (size_t)r*HD + cg);
    }
    // prefetch s-tile 0 (K,V: 64 rows x 64 each)
    #pragma unroll
    for (int p = 0; p < 2; p++) {
        int u = tid + p*256;
        int r = u >> 3, cg = (u & 7) * 8;
        cp16(&Ks[0][r][cg], Kg + (size_t)r*HD + cg);
        cp16(&Vs[0][r][cg], Vg + (size_t)r*TOK + cg);
    }
    CP_COMMIT();
    __syncthreads();

    uint32_t aq[4][4];
    #pragma unroll
    for (int kk = 0; kk < 4; kk++) {
        int mr = wid*16 + g, kc = kk*16 + tg*2;
        aq[kk][0] = *(const uint32_t*)&Qs[mr  ][kc];
        aq[kk][1] = *(const uint32_t*)&Qs[mr+8][kc];
        aq[kk][2] = *(const uint32_t*)&Qs[mr  ][kc+8];
        aq[kk][3] = *(const uint32_t*)&Qs[mr+8][kc+8];
    }

    float l0 = 0.f, l1 = 0.f;          // per-lane partial row sums
    float o[8][4] = {};

    for (int it = 0; it < 16; it++) {
        int buf = it & 1;
        if (it + 1 < 16) {
            int s1 = (it+1)*64;
            #pragma unroll
            for (int p = 0; p < 2; p++) {
                int u = tid + p*256;
                int r = u >> 3, cg = (u & 7) * 8;
                cp16(&Ks[buf^1][r][cg], Kg + (size_t)(s1+r)*HD + cg);
                cp16(&Vs[buf^1][r][cg], Vg + (size_t)r*TOK + s1 + cg);
            }
            CP_COMMIT();
            CP_WAIT1();
        } else {
            CP_WAIT0();
        }
        __syncthreads();

        // S = Q K^T  (log2 domain, pre-scaled)
        float sc[8][4] = {};
        #pragma unroll
        for (int kk = 0; kk < 4; kk++) {
            int kc = kk*16 + tg*2;
            #pragma unroll
            for (int j = 0; j < 8; j++) {
                uint32_t bf[2];
                bf[0] = *(const uint32_t*)&Ks[buf][j*8+g][kc];
                bf[1] = *(const uint32_t*)&Ks[buf][j*8+g][kc+8];
                mma_f16(sc[j], aq[kk], bf);
            }
        }

        // P = 2^(S - SM_OFF); accumulate per-lane partial sums only
        #pragma unroll
        for (int j = 0; j < 8; j++) {
            sc[j][0] = ex2(sc[j][0] - SM_OFF);
            sc[j][1] = ex2(sc[j][1] - SM_OFF);
            sc[j][2] = ex2(sc[j][2] - SM_OFF);
            sc[j][3] = ex2(sc[j][3] - SM_OFF);
            l0 += sc[j][0] + sc[j][1];
            l1 += sc[j][2] + sc[j][3];
        }

        // O += P V
        #pragma unroll
        for (int i = 0; i < 4; i++) {
            uint32_t ap[4];
            ap[0] = pack_h2(sc[2*i  ][0], sc[2*i  ][1]);
            ap[1] = pack_h2(sc[2*i  ][2], sc[2*i  ][3]);
            ap[2] = pack_h2(sc[2*i+1][0], sc[2*i+1][1]);
            ap[3] = pack_h2(sc[2*i+1][2], sc[2*i+1][3]);
            int kc = i*16 + tg*2;
            #pragma unroll
            for (int jc = 0; jc < 8; jc++) {
                uint32_t bf[2];
                bf[0] = *(const uint32_t*)&Vs[buf][jc*8+g][kc];
                bf[1] = *(const uint32_t*)&Vs[buf][jc*8+g][kc+8];
                mma_f16(o[jc], ap, bf);
            }
        }
        __syncthreads();
    }

    // finalize row sums across the 4 tg-lanes of each row
    l0 += __shfl_xor_sync(~0u, l0, 1);
    l0 += __shfl_xor_sync(~0u, l0, 2);
    l1 += __shfl_xor_sync(~0u, l1, 1);
    l1 += __shfl_xor_sync(~0u, l1, 2);
    float inv0 = 1.f / l0, inv1 = 1.f / l1;

    int t = t0 + wid*16 + g;
    size_t rowbase = (size_t)b*TOK;
    #pragma unroll
    for (int jc = 0; jc < 8; jc++) {
        int cc = h*HD + jc*8 + tg*2;
        *(__half2*)&g_netT[(rowbase + t  )*CH + cc] =
            __floats2half2_rn(o[jc][0]*inv0, o[jc][1]*inv0);
        *(__half2*)&g_netT[(rowbase + t+8)*CH + cc] =
            __floats2half2_rn(o[jc][2]*inv1, o[jc][3]*inv1);
    }
}

// ---------------------------------------------------------------------------
extern "C" void kernel_launch(void* const* d_in, const int* in_sizes, int n_in,
                              void* d_out, int out_size)
{
    const float* x     = (const float*)d_in[0];
    const float* gn_w  = (const float*)d_in[1];
    const float* gn_b  = (const float*)d_in[2];
    const float* qkv_w = (const float*)d_in[3];
    const float* qkv_b = (const float*)d_in[4];
    const float* out_w = (const float*)d_in[5];
    const float* out_b = (const float*)d_in[6];
    float* out = (float*)d_out;

    __half *nT, *wqkv, *wout, *netT;
    cudaGetSymbolAddress((void**)&nT,   g_nT);
    cudaGetSymbolAddress((void**)&wqkv, g_wqkv);
    cudaGetSymbolAddress((void**)&wout, g_wout);
    cudaGetSymbolAddress((void**)&netT, g_netT);

    cvt_w_kernel<<<1024, 256>>>(qkv_w, out_w);
    gn_kernel<<<BATCH*GROUPS, 256>>>(x, gn_w, gn_b);
    gemm_h<0><<<dim3(12, 8, BATCH), 256>>>(nT, wqkv, qkv_b, nullptr, nullptr);
    flash_kernel<<<dim3(8, NHEAD), 256>>>();
    gemm_h<1><<<dim3(8, 4, BATCH), 256>>>(wout, netT, out_b, x, out);
}

// round 6
// speedup vs baseline: 1.0673x; 1.0673x over previous
#include <cuda_runtime.h>
#include <cuda_fp16.h>
#include <cstddef>
#include <cstdint>

#define BATCH 8
#define CH    512
#define TOK   1024
#define HEADS 8
#define HD    64
#define NHEAD (BATCH*HEADS)   // 64
#define GROUPS 32
#define CPG   16

#define QSCALE 0.1803368801111204f   // 0.125 * log2(e)

// ---------------- scratch (__device__ globals; alloc-free rule) -------------
__device__ __align__(16) __half g_nT  [(size_t)BATCH*TOK*CH];    // [b][t][c]
__device__ __align__(16) __half g_wqkv[(size_t)3*CH*CH];         // [och][c]
__device__ __align__(16) __half g_wout[(size_t)CH*CH];           // [och][c]
__device__ __align__(16) __half g_q   [(size_t)NHEAD*TOK*HD];    // [head][t][c]  (x QSCALE)
__device__ __align__(16) __half g_k   [(size_t)NHEAD*TOK*HD];    // [head][s][c]
__device__ __align__(16) __half g_v   [(size_t)NHEAD*HD*TOK];    // [head][c][s]
__device__ __align__(16) __half g_netT[(size_t)BATCH*TOK*CH];    // [b][t][c]

// ---------------- helpers ---------------------------------------------------
__device__ __forceinline__ void mma_f16(float* c, const uint32_t* a, const uint32_t* b)
{
    asm volatile(
        "mma.sync.aligned.m16n8k16.row.col.f32.f16.f16.f32 "
        "{%0,%1,%2,%3},{%4,%5,%6,%7},{%8,%9},{%0,%1,%2,%3};"
        : "+f"(c[0]), "+f"(c[1]), "+f"(c[2]), "+f"(c[3])
        : "r"(a[0]), "r"(a[1]), "r"(a[2]), "r"(a[3]), "r"(b[0]), "r"(b[1]));
}

// P = 2^(half2(lo,hi) - 2): cvt f32x2->f16x2, shift (cancels in O/l), packed ex2
__device__ __forceinline__ uint32_t h2p(float lo, float hi)
{
    uint32_t d;
    asm("cvt.rn.f16x2.f32 %0, %1, %2;" : "=r"(d) : "f"(hi), "f"(lo));
    asm("add.f16x2 %0, %0, %1;" : "+r"(d) : "r"(0xC000C000u));   // (-2,-2)
    asm("ex2.approx.f16x2 %0, %0;" : "+r"(d));
    return d;
}

__device__ __forceinline__ void cp16(void* s, const void* g)
{
    uint32_t sa = (uint32_t)__cvta_generic_to_shared(s);
    asm volatile("cp.async.cg.shared.global [%0], [%1], 16;\n" :: "r"(sa), "l"(g));
}
#define CP_COMMIT() asm volatile("cp.async.commit_group;\n" ::: "memory")
#define CP_WAIT1()  asm volatile("cp.async.wait_group 1;\n" ::: "memory")
#define CP_WAIT0()  asm volatile("cp.async.wait_group 0;\n" ::: "memory")

// ---------------------------------------------------------------------------
// Kernel 1: fused prep. Blocks 0..255: GroupNorm -> g_nT (transposed half).
// Blocks 256..1279: weight fp32->fp16 conversion.
// ---------------------------------------------------------------------------
__global__ void prep_kernel(const float* __restrict__ x,
                            const float* __restrict__ w,
                            const float* __restrict__ bb,
                            const float* __restrict__ qkvw,
                            const float* __restrict__ outw)
{
    int tid = threadIdx.x;
    if (blockIdx.x >= 256) {
        int i = (blockIdx.x - 256) * 256 + tid;
        const int N1 = 3*CH*CH/4;
        const int N2 = CH*CH/4;
        if (i < N1) {
            float4 v = *(const float4*)(qkvw + (size_t)i*4);
            __half* d = g_wqkv + (size_t)i*4;
            d[0]=__float2half_rn(v.x); d[1]=__float2half_rn(v.y);
            d[2]=__float2half_rn(v.z); d[3]=__float2half_rn(v.w);
        } else if (i < N1 + N2) {
            int j = i - N1;
            float4 v = *(const float4*)(outw + (size_t)j*4);
            __half* d = g_wout + (size_t)j*4;
            d[0]=__float2half_rn(v.x); d[1]=__float2half_rn(v.y);
            d[2]=__float2half_rn(v.z); d[3]=__float2half_rn(v.w);
        }
        return;
    }

    int blk = blockIdx.x;
    int b = blk >> 5, gg = blk & 31;
    const float* src = x + ((size_t)b*CH + gg*CPG) * TOK;
    const int N = CPG * TOK;   // 16384

    float s = 0.f, ss = 0.f;
    for (int i = tid*4; i < N; i += 256*4) {
        float4 v = *(const float4*)(src + i);
        s  += v.x + v.y + v.z + v.w;
        ss += v.x*v.x + v.y*v.y + v.z*v.z + v.w*v.w;
    }
    for (int o = 16; o; o >>= 1) {
        s  += __shfl_down_sync(~0u, s,  o);
        ss += __shfl_down_sync(~0u, ss, o);
    }
    __shared__ float shs[8], shq[8];
    __shared__ float f_mu, f_rstd;
    if ((tid & 31) == 0) { shs[tid>>5] = s; shq[tid>>5] = ss; }
    __syncthreads();
    if (tid == 0) {
        float ts = 0.f, tq = 0.f;
        #pragma unroll
        for (int i = 0; i < 8; i++) { ts += shs[i]; tq += shq[i]; }
        float mu  = ts / N;
        f_mu = mu;
        f_rstd = rsqrtf(tq / N - mu*mu + 1e-5f);
    }
    __syncthreads();
    float mu = f_mu, rstd = f_rstd;

    __shared__ __align__(16) __half tile[16][68];
    int c  = tid >> 4;
    int tl = (tid & 15) * 4;
    float scw = w[gg*CPG + c] * rstd;
    float scb = bb[gg*CPG + c] - mu * scw;
    int tw  = tid >> 2;
    int c4  = (tid & 3) * 4;
    for (int t0 = 0; t0 < TOK; t0 += 64) {
        float4 v = *(const float4*)(src + (size_t)c*TOK + t0 + tl);
        __half2 h0 = __floats2half2_rn(v.x*scw+scb, v.y*scw+scb);
        __half2 h1 = __floats2half2_rn(v.z*scw+scb, v.w*scw+scb);
        *(__half2*)&tile[c][tl]   = h0;
        *(__half2*)&tile[c][tl+2] = h1;
        __syncthreads();
        __half* dst = g_nT + ((size_t)b*TOK + t0 + tw)*CH + gg*CPG + c4;
        *(__half2*)(dst)   = __halves2half2(tile[c4  ][tw], tile[c4+1][tw]);
        *(__half2*)(dst+2) = __halves2half2(tile[c4+2][tw], tile[c4+3][tw]);
        __syncthreads();
    }
}

// ---------------------------------------------------------------------------
// Kernel 2/4: half GEMM, C[m][n] = sum_k A[m][k] * B[n][k], K=512.
// 128x128 block tile, 8 warps, double-buffered smem via cp.async.
// ---------------------------------------------------------------------------
template<int MODE>
__global__ void __launch_bounds__(256)
gemm_h(const __half* __restrict__ Abase, const __half* __restrict__ Bbase,
       const float* __restrict__ bias, const float* __restrict__ res,
       float* __restrict__ Cout)
{
    __shared__ __align__(16) __half As[2][128][40];
    __shared__ __align__(16) __half Bs[2][128][40];

    int bz = blockIdx.z;
    const __half* A = Abase + (MODE == 0 ? (size_t)bz*TOK*CH : 0);
    const __half* B = Bbase + (MODE == 1 ? (size_t)bz*TOK*CH : 0);

    int m0 = blockIdx.y * 128, n0 = blockIdx.x * 128;
    int tid = threadIdx.x, wid = tid >> 5, lane = tid & 31;
    int g = lane >> 2, tg = lane & 3;
    int wm = wid & 3, wn = wid >> 2;

    int lr = tid >> 2;
    int lc = (tid & 3) * 8;

    cp16(&As[0][lr   ][lc], A + (size_t)(m0+lr   )*CH + lc);
    cp16(&As[0][lr+64][lc], A + (size_t)(m0+lr+64)*CH + lc);
    cp16(&Bs[0][lr   ][lc], B + (size_t)(n0+lr   )*CH + lc);
    cp16(&Bs[0][lr+64][lc], B + (size_t)(n0+lr+64)*CH + lc);
    CP_COMMIT();

    float acc[2][8][4] = {};

    for (int ks = 0; ks < 16; ks++) {
        int buf = ks & 1;
        if (ks + 1 < 16) {
            int k1 = (ks+1) * 32;
            cp16(&As[buf^1][lr   ][lc], A + (size_t)(m0+lr   )*CH + k1 + lc);
            cp16(&As[buf^1][lr+64][lc], A + (size_t)(m0+lr+64)*CH + k1 + lc);
            cp16(&Bs[buf^1][lr   ][lc], B + (size_t)(n0+lr   )*CH + k1 + lc);
            cp16(&Bs[buf^1][lr+64][lc], B + (size_t)(n0+lr+64)*CH + k1 + lc);
            CP_COMMIT();
            CP_WAIT1();
        } else {
            CP_WAIT0();
        }
        __syncthreads();
        #pragma unroll
        for (int kk = 0; kk < 2; kk++) {
            uint32_t af[2][4], bf[8][2];
            int kc = kk*16 + tg*2;
            #pragma unroll
            for (int i = 0; i < 2; i++) {
                int mr = wm*32 + i*16 + g;
                af[i][0] = *(const uint32_t*)&As[buf][mr  ][kc];
                af[i][1] = *(const uint32_t*)&As[buf][mr+8][kc];
                af[i][2] = *(const uint32_t*)&As[buf][mr  ][kc+8];
                af[i][3] = *(const uint32_t*)&As[buf][mr+8][kc+8];
            }
            #pragma unroll
            for (int j = 0; j < 8; j++) {
                int nr = wn*64 + j*8 + g;
                bf[j][0] = *(const uint32_t*)&Bs[buf][nr][kc];
                bf[j][1] = *(const uint32_t*)&Bs[buf][nr][kc+8];
            }
            #pragma unroll
            for (int i = 0; i < 2; i++)
                #pragma unroll
                for (int j = 0; j < 8; j++)
                    mma_f16(acc[i][j], af[i], bf[j]);
        }
        __syncthreads();
    }

    if (MODE == 0) {
        #pragma unroll
        for (int j = 0; j < 8; j++) {
            int n = n0 + wn*64 + j*8 + tg*2;      // och
            float bi0 = bias[n], bi1 = bias[n+1];
            int hh = n / 192, r = n % 192;
            #pragma unroll
            for (int i = 0; i < 2; i++) {
                int t = m0 + wm*32 + i*16 + g;
                float v00 = acc[i][j][0]+bi0, v01 = acc[i][j][1]+bi1;
                float v10 = acc[i][j][2]+bi0, v11 = acc[i][j][3]+bi1;
                size_t hb = (size_t)(bz*HEADS + hh);
                if (r < 64) {
                    v00*=QSCALE; v01*=QSCALE; v10*=QSCALE; v11*=QSCALE;
                    __half* q = g_q + (hb*TOK)*HD + r;
                    *(__half2*)(q + (size_t)t    *HD) = __floats2half2_rn(v00, v01);
                    *(__half2*)(q + (size_t)(t+8)*HD) = __floats2half2_rn(v10, v11);
                } else if (r < 128) {
                    __half* k = g_k + (hb*TOK)*HD + (r-64);
                    *(__half2*)(k + (size_t)t    *HD) = __floats2half2_rn(v00, v01);
                    *(__half2*)(k + (size_t)(t+8)*HD) = __floats2half2_rn(v10, v11);
                } else {
                    int cc = r - 128;
                    __half* v = g_v + (hb*HD + cc)*TOK;
                    v[t]         = __float2half_rn(v00);
                    v[TOK + t]   = __float2half_rn(v01);
                    v[t+8]       = __float2half_rn(v10);
                    v[TOK + t+8] = __float2half_rn(v11);
                }
            }
        }
    } else {
        #pragma unroll
        for (int j = 0; j < 8; j++) {
            int n = n0 + wn*64 + j*8 + tg*2;
            #pragma unroll
            for (int i = 0; i < 2; i++) {
                int m = m0 + wm*32 + i*16 + g;
                float ob0 = bias[m], ob1 = bias[m+8];
                size_t o0 = ((size_t)bz*CH + m)*TOK + n;
                size_t o1 = ((size_t)bz*CH + m+8)*TOK + n;
                float2 r0 = *(const float2*)(res + o0);
                float2 r1 = *(const float2*)(res + o1);
                float2 w0 = { acc[i][j][0]+ob0+r0.x, acc[i][j][1]+ob0+r0.y };
                float2 w1 = { acc[i][j][2]+ob1+r1.x, acc[i][j][3]+ob1+r1.y };
                *(float2*)(Cout + o0) = w0;
                *(float2*)(Cout + o1) = w1;
            }
        }
    }
}

// ---------------------------------------------------------------------------
// Kernel 3: flash attention. Block = (head, 64 q-rows), 128 thr / 4 warps.
// Static-shift softmax fully in f16x2 MUFU; row sums via ones-column MMA
// (exact fp32 denominator from the tensor pipe). K/V double-buffered cp.async.
// ---------------------------------------------------------------------------
__global__ void __launch_bounds__(128) flash_kernel()
{
    int head = blockIdx.y;
    int b = head >> 3, h = head & 7;
    int t0 = blockIdx.x * 64;
    const __half* Qg = g_q + ((size_t)head*TOK + t0)*HD;
    const __half* Kg = g_k + (size_t)head*TOK*HD;
    const __half* Vg = g_v + (size_t)head*HD*TOK;

    __shared__ __align__(16) __half Qs[64][72];
    __shared__ __align__(16) __half Ks[2][64][72];
    __shared__ __align__(16) __half Vs[2][64][72];

    int tid = threadIdx.x, wid = tid >> 5, lane = tid & 31;
    int g = lane >> 2, tg = lane & 3;

    #pragma unroll
    for (int p = 0; p < 4; p++) {
        int u = tid + p*128;
        int r = u >> 3, cg = (u & 7) * 8;
        *(uint4*)&Qs[r][cg] = *(const uint4*)(Qg + (size_t)r*HD + cg);
    }
    #pragma unroll
    for (int p = 0; p < 4; p++) {
        int u = tid + p*128;
        int r = u >> 3, cg = (u & 7) * 8;
        cp16(&Ks[0][r][cg], Kg + (size_t)r*HD + cg);
        cp16(&Vs[0][r][cg], Vg + (size_t)r*TOK + cg);
    }
    CP_COMMIT();
    __syncthreads();

    uint32_t aq[4][4];
    #pragma unroll
    for (int kk = 0; kk < 4; kk++) {
        int mr = wid*16 + g, kc = kk*16 + tg*2;
        aq[kk][0] = *(const uint32_t*)&Qs[mr  ][kc];
        aq[kk][1] = *(const uint32_t*)&Qs[mr+8][kc];
        aq[kk][2] = *(const uint32_t*)&Qs[mr  ][kc+8];
        aq[kk][3] = *(const uint32_t*)&Qs[mr+8][kc+8];
    }

    const uint32_t ones2 = 0x3C003C00u;    // half2(1,1)
    float o[8][4] = {};
    float ol[4] = {};                      // row-sum accumulator (ones column)

    for (int it = 0; it < 16; it++) {
        int buf = it & 1;
        if (it + 1 < 16) {
            int s1 = (it+1)*64;
            #pragma unroll
            for (int p = 0; p < 4; p++) {
                int u = tid + p*128;
                int r = u >> 3, cg = (u & 7) * 8;
                cp16(&Ks[buf^1][r][cg], Kg + (size_t)(s1+r)*HD + cg);
                cp16(&Vs[buf^1][r][cg], Vg + (size_t)r*TOK + s1 + cg);
            }
            CP_COMMIT();
            CP_WAIT1();
        } else {
            CP_WAIT0();
        }
        __syncthreads();

        // S = Q K^T  (log2 domain, pre-scaled)
        float sc[8][4] = {};
        #pragma unroll
        for (int kk = 0; kk < 4; kk++) {
            int kc = kk*16 + tg*2;
            #pragma unroll
            for (int j = 0; j < 8; j++) {
                uint32_t bf[2];
                bf[0] = *(const uint32_t*)&Ks[buf][j*8+g][kc];
                bf[1] = *(const uint32_t*)&Ks[buf][j*8+g][kc+8];
                mma_f16(sc[j], aq[kk], bf);
            }
        }

        // P = 2^(S-2) in packed half2 (shift cancels exactly in O/l)
        uint32_t ph[8][2];
        #pragma unroll
        for (int j = 0; j < 8; j++) {
            ph[j][0] = h2p(sc[j][0], sc[j][1]);   // row g
            ph[j][1] = h2p(sc[j][2], sc[j][3]);   // row g+8
        }

        // O += P V ; ol += P * ones (row sums, exact, same rounding as O)
        #pragma unroll
        for (int i = 0; i < 4; i++) {
            uint32_t ap[4];
            ap[0] = ph[2*i  ][0];
            ap[1] = ph[2*i  ][1];
            ap[2] = ph[2*i+1][0];
            ap[3] = ph[2*i+1][1];
            int kc = i*16 + tg*2;
            #pragma unroll
            for (int jc = 0; jc < 8; jc++) {
                uint32_t bf[2];
                bf[0] = *(const uint32_t*)&Vs[buf][jc*8+g][kc];
                bf[1] = *(const uint32_t*)&Vs[buf][jc*8+g][kc+8];
                mma_f16(o[jc], ap, bf);
            }
            uint32_t bo[2] = { ones2, ones2 };
            mma_f16(ol, ap, bo);
        }
        __syncthreads();
    }

    float inv0 = 1.f / ol[0], inv1 = 1.f / ol[2];
    int t = t0 + wid*16 + g;
    size_t rowbase = (size_t)b*TOK;
    #pragma unroll
    for (int jc = 0; jc < 8; jc++) {
        int cc = h*HD + jc*8 + tg*2;
        *(__half2*)&g_netT[(rowbase + t  )*CH + cc] =
            __floats2half2_rn(o[jc][0]*inv0, o[jc][1]*inv0);
        *(__half2*)&g_netT[(rowbase + t+8)*CH + cc] =
            __floats2half2_rn(o[jc][2]*inv1, o[jc][3]*inv1);
    }
}

// ---------------------------------------------------------------------------
extern "C" void kernel_launch(void* const* d_in, const int* in_sizes, int n_in,
                              void* d_out, int out_size)
{
    const float* x     = (const float*)d_in[0];
    const float* gn_w  = (const float*)d_in[1];
    const float* gn_b  = (const float*)d_in[2];
    const float* qkv_w = (const float*)d_in[3];
    const float* qkv_b = (const float*)d_in[4];
    const float* out_w = (const float*)d_in[5];
    const float* out_b = (const float*)d_in[6];
    float* out = (float*)d_out;

    __half *nT, *wqkv, *wout, *netT;
    cudaGetSymbolAddress((void**)&nT,   g_nT);
    cudaGetSymbolAddress((void**)&wqkv, g_wqkv);
    cudaGetSymbolAddress((void**)&wout, g_wout);
    cudaGetSymbolAddress((void**)&netT, g_netT);

    prep_kernel<<<1280, 256>>>(x, gn_w, gn_b, qkv_w, out_w);
    gemm_h<0><<<dim3(12, 8, BATCH), 256>>>(nT, wqkv, qkv_b, nullptr, nullptr);
    flash_kernel<<<dim3(16, NHEAD), 128>>>();
    gemm_h<1><<<dim3(8, 4, BATCH), 256>>>(wout, netT, out_b, x, out);
}